// round 16
// baseline (speedup 1.0000x reference)
#include <cuda_runtime.h>
#include <math_constants.h>
#include <stdint.h>

// Problem constants
#define BB 2
#define SS 2048
#define DD 1024
#define HH 16
#define HDIM 64
#define MROWS (BB * SS)      // 4096
#define NQKV (3 * DD)        // 3072

// Scratch (allocation-free rule: __device__ globals)
// k-pair permutation pi(j) = 2*(j&3) + (j>>2) applied within 8-groups of the
// contraction index on A-operand producers:
//   g_xr   : x with D-columns permuted
//   g_qkv  : Q,K thirds have HD-columns permuted; V third plain
//   g_attn : D-columns permuted (feeds outproj A)
__device__ float g_qkv[(size_t)MROWS * NQKV];
__device__ float g_attn[(size_t)MROWS * DD];
__device__ float g_xr[(size_t)MROWS * DD];
__device__ float g_wqkvr[(size_t)DD * NQKV];    // tf32-rounded w_qkv (plain)
__device__ float g_woutr[(size_t)DD * DD];      // tf32-rounded w_out (plain)

__device__ __forceinline__ uint32_t f2tf32(float f) {
    uint32_t u;
    asm("cvt.rna.tf32.f32 %0, %1;" : "=r"(u) : "f"(f));
    return u;
}

__device__ __forceinline__ float ex2(float x) {
    float r;
    asm("ex2.approx.f32 %0, %1;" : "=f"(r) : "f"(x));
    return r;
}

__device__ __forceinline__ void mma_tf32(float d[4],
                                         uint32_t a0, uint32_t a1, uint32_t a2, uint32_t a3,
                                         uint32_t b0, uint32_t b1) {
    asm volatile(
        "mma.sync.aligned.m16n8k8.row.col.f32.tf32.tf32.f32 "
        "{%0,%1,%2,%3}, {%4,%5,%6,%7}, {%8,%9}, {%0,%1,%2,%3};"
        : "+f"(d[0]), "+f"(d[1]), "+f"(d[2]), "+f"(d[3])
        : "r"(a0), "r"(a1), "r"(a2), "r"(a3), "r"(b0), "r"(b1));
}

__device__ __forceinline__ void cp16(uint32_t dst_smem, const void* src) {
    asm volatile("cp.async.cg.shared.global [%0], [%1], 16;"
                 :: "r"(dst_smem), "l"(src));
}
__device__ __forceinline__ void cp_commit() {
    asm volatile("cp.async.commit_group;" ::: "memory");
}
template <int N>
__device__ __forceinline__ void cp_wait_n() {
    asm volatile("cp.async.wait_group %0;" :: "n"(N) : "memory");
}
__device__ __forceinline__ void cp_wait(int pending) {
    if (pending) asm volatile("cp.async.wait_group 1;" ::: "memory");
    else         asm volatile("cp.async.wait_group 0;" ::: "memory");
}

// ---------------------------------------------------------------------------
// Pre-round inputs to tf32. x additionally gets the k-pair permutation:
// per 8-group [j0..j7] -> [j0,j4,j1,j5,j2,j6,j3,j7].
// ---------------------------------------------------------------------------
__global__ __launch_bounds__(256)
void pre_round(const float4* __restrict__ x,
               const float4* __restrict__ wq,
               const float4* __restrict__ wo)
{
    const int NX8 = (MROWS * DD) / 8;       // 8-float granules of x
    const int NQ  = (DD * NQKV) / 4;
    const int NO  = (DD * DD) / 4;
    for (int i = blockIdx.x * blockDim.x + threadIdx.x;
         i < NX8 + NQ + NO; i += gridDim.x * blockDim.x) {
        if (i < NX8) {
            float4 lo = x[2 * i], hi = x[2 * i + 1];
            uint4 t0 = make_uint4(f2tf32(lo.x), f2tf32(hi.x), f2tf32(lo.y), f2tf32(hi.y));
            uint4 t1 = make_uint4(f2tf32(lo.z), f2tf32(hi.z), f2tf32(lo.w), f2tf32(hi.w));
            ((float4*)g_xr)[2 * i]     = *reinterpret_cast<float4*>(&t0);
            ((float4*)g_xr)[2 * i + 1] = *reinterpret_cast<float4*>(&t1);
        } else if (i < NX8 + NQ) {
            float4 v = wq[i - NX8];
            uint4 t = make_uint4(f2tf32(v.x), f2tf32(v.y), f2tf32(v.z), f2tf32(v.w));
            ((float4*)g_wqkvr)[i - NX8] = *reinterpret_cast<float4*>(&t);
        } else {
            float4 v = wo[i - NX8 - NQ];
            uint4 t = make_uint4(f2tf32(v.x), f2tf32(v.y), f2tf32(v.z), f2tf32(v.w));
            ((float4*)g_woutr)[i - NX8 - NQ] = *reinterpret_cast<float4*>(&t);
        }
    }
}

// ---------------------------------------------------------------------------
// TF32 tensor-core GEMM, 3-stage cp.async pipeline (unchanged champion).
// ---------------------------------------------------------------------------
#define ASTR 40
#define ASZ (128 * ASTR)
#define BSZ (32 * 136)
#define STAGE (ASZ + BSZ)

template <int MODE>
__global__ __launch_bounds__(256, 2)
void mma_gemm(float* __restrict__ Cp)
{
    extern __shared__ uint32_t dynsmem[];
    constexpr int N_ = (MODE == 0) ? NQKV : DD;
    constexpr int K_ = DD;
    constexpr int NK = K_ / 32;            // 32

    const float* A  = (MODE == 0) ? (const float*)g_xr    : (const float*)g_attn;
    const float* Bm = (MODE == 0) ? (const float*)g_wqkvr : (const float*)g_woutr;
    float* C = (MODE == 0) ? (float*)g_qkv : Cp;

    const int tid  = threadIdx.x;
    const int warp = tid >> 5;
    const int lane = tid & 31;
    const int r = lane >> 2;
    const int c = lane & 3;

    const int bm = blockIdx.y * 128;
    const int bn = blockIdx.x * 128;
    const int wm = (warp >> 2) * 64;
    const int wn = (warp & 3) * 32;

    const uint32_t smem_base = (uint32_t)__cvta_generic_to_shared(dynsmem);

    float acc[4][4][4] = {};

    auto load_tiles = [&](int st, int k0) {
        uint32_t abase = smem_base + (uint32_t)(st * STAGE) * 4u;
        uint32_t bbase = abase + (uint32_t)ASZ * 4u;
        #pragma unroll
        for (int p = 0; p < 4; p++) {
            int f4 = tid + p * 256;
            int rr = f4 >> 3;
            int cc = (f4 & 7) << 2;
            cp16(abase + (uint32_t)(rr * ASTR + cc) * 4u,
                 A + (size_t)(bm + rr) * K_ + k0 + cc);
        }
        #pragma unroll
        for (int p = 0; p < 4; p++) {
            int f4 = tid + p * 256;
            int rr = f4 >> 5;
            int cc = (f4 & 31) << 2;
            cp16(bbase + (uint32_t)(rr * 136 + cc) * 4u,
                 Bm + (size_t)(k0 + rr) * N_ + bn + cc);
        }
        cp_commit();
    };

    load_tiles(0, 0);
    load_tiles(1, 32);

    int st = 0;
    for (int i = 0; i < NK; i++) {
        if (i + 1 < NK) cp_wait_n<1>();   // load(i) complete; load(i+1) in flight
        else            cp_wait_n<0>();
        __syncthreads();                  // compute(i-1) readers of buf st2 done
        if (i + 2 < NK) {
            int st2 = st + 2; if (st2 >= 3) st2 -= 3;
            load_tiles(st2, (i + 2) << 5);
        }

        const uint32_t* Asb = dynsmem + st * STAGE;
        const uint32_t* Bsb = Asb + ASZ;

        #pragma unroll
        for (int ks = 0; ks < 4; ks++) {
            const int kk = ks * 8;
            uint32_t af[4][4], bf[4][2];
            #pragma unroll
            for (int mi = 0; mi < 4; mi++) {
                int row = wm + mi * 16 + r;
                uint2 aa0 = *reinterpret_cast<const uint2*>(&Asb[row * ASTR + kk + 2 * c]);
                uint2 aa1 = *reinterpret_cast<const uint2*>(&Asb[(row + 8) * ASTR + kk + 2 * c]);
                af[mi][0] = aa0.x; af[mi][1] = aa1.x;
                af[mi][2] = aa0.y; af[mi][3] = aa1.y;
            }
            #pragma unroll
            for (int ni = 0; ni < 4; ni++) {
                int col = wn + ni * 8 + r;
                bf[ni][0] = Bsb[(kk + c) * 136 + col];
                bf[ni][1] = Bsb[(kk + c + 4) * 136 + col];
            }
            #pragma unroll
            for (int mi = 0; mi < 4; mi++)
                #pragma unroll
                for (int ni = 0; ni < 4; ni++)
                    mma_tf32(acc[mi][ni], af[mi][0], af[mi][1], af[mi][2], af[mi][3],
                             bf[ni][0], bf[ni][1]);
        }
        if (++st == 3) st = 0;
    }

    const int p0 = ((2 * c) & 3) * 2 + ((2 * c) >> 2);
    const int p1 = ((2 * c + 1) & 3) * 2 + ((2 * c + 1) >> 2);
    #pragma unroll
    for (int mi = 0; mi < 4; mi++) {
        int row0 = bm + wm + mi * 16 + r;
        #pragma unroll
        for (int ni = 0; ni < 4; ni++) {
            if (MODE == 0) {
                uint32_t v0 = f2tf32(acc[mi][ni][0]);
                uint32_t v1 = f2tf32(acc[mi][ni][1]);
                uint32_t v2 = f2tf32(acc[mi][ni][2]);
                uint32_t v3 = f2tf32(acc[mi][ni][3]);
                if (bn < 2 * DD) {     // Q or K third: permuted scatter
                    int gb = bn + wn + ni * 8;
                    uint32_t* c0 = (uint32_t*)(C + (size_t)row0 * N_ + gb);
                    uint32_t* c1 = (uint32_t*)(C + (size_t)(row0 + 8) * N_ + gb);
                    c0[p0] = v0;  c0[p1] = v1;
                    c1[p0] = v2;  c1[p1] = v3;
                } else {               // V third: plain
                    int col = bn + wn + ni * 8 + c * 2;
                    *reinterpret_cast<uint2*>(C + (size_t)row0 * N_ + col) = make_uint2(v0, v1);
                    *reinterpret_cast<uint2*>(C + (size_t)(row0 + 8) * N_ + col) = make_uint2(v2, v3);
                }
            } else {
                int col = bn + wn + ni * 8 + c * 2;
                *reinterpret_cast<float2*>(Cp + (size_t)row0 * N_ + col) =
                    make_float2(acc[mi][ni][0], acc[mi][ni][1]);
                *reinterpret_cast<float2*>(Cp + (size_t)(row0 + 8) * N_ + col) =
                    make_float2(acc[mi][ni][2], acc[mi][ni][3]);
            }
        }
    }
}

// ---------------------------------------------------------------------------
// TF32 causal flash attention — register-P, log2 softmax (R14 math, bit-exact),
// now with 128-row q-tiles and 8 warps/CTA: each 64x64 K/V tile in smem serves
// 128 q-rows instead of 64, halving per-row smem-read and gmem traffic.
// Warp w owns q-rows [16w, 16w+16); per-warp math identical to R14.
// Key tiles remain 64 wide: nkt = 2*qt+2; mask only on the last two tiles.
// Sync: same 2-barrier double-buffered loop as the champion.
// Smem unchanged (73728 B) -> 2 CTAs/SM x 256 thr = 16 warps/SM (vs 12).
// ---------------------------------------------------------------------------
#define KST 72
#define VST 72
#define KPSZ (64 * KST)
#define VSZ  (64 * VST)

__global__ __launch_bounds__(256, 2)
void attn_mma(void)
{
    extern __shared__ uint32_t dynsmem[];

    const int tid = threadIdx.x;
    const int w  = tid >> 5;             // 0..7
    const int l  = tid & 31;
    const int lr = l >> 2;
    const int lc = l & 3;
    const int qt = gridDim.x - 1 - blockIdx.x;   // long blocks first, 0..15
    const int h  = blockIdx.y;
    const int b  = blockIdx.z;
    const int ldq = NQKV;

    const float* qb  = g_qkv + ((size_t)b * SS + (size_t)qt * 128) * ldq + h * HDIM;
    const float* kb0 = g_qkv + (size_t)b * SS * ldq + DD + h * HDIM;
    const float* vb0 = g_qkv + (size_t)b * SS * ldq + 2 * DD + h * HDIM;

    const uint32_t smem_base = (uint32_t)__cvta_generic_to_shared(dynsmem);

    // 64x64 K and V tiles: 1024 float4 each; 256 threads -> 4 cp16 per tile each
    auto load_kv = [&](int st, int kt) {
        const float* kb = kb0 + (size_t)kt * 64 * ldq;
        const float* vb = vb0 + (size_t)kt * 64 * ldq;
        uint32_t kbase = smem_base + (uint32_t)(st * KPSZ) * 4u;
        uint32_t vbase = smem_base + (uint32_t)(2 * KPSZ + st * VSZ) * 4u;
        #pragma unroll
        for (int p = 0; p < 4; p++) {
            int f4 = tid + p * 256;
            int r  = f4 >> 4;
            int c4 = (f4 & 15) << 2;
            cp16(kbase + (uint32_t)(r * KST + c4) * 4u, kb + (size_t)r * ldq + c4);
            // V: permuted key-row slot  sigma(r&7) = 4*(r&1) + ((r&7)>>1)
            int vr = (r & 56) | (((r & 1) << 2) | ((r & 7) >> 1));
            cp16(vbase + (uint32_t)(vr * VST + c4) * 4u, vb + (size_t)r * ldq + c4);
        }
        cp_commit();
    };

    // Q fragments: permuted pair (2lc,2lc+1) == original (d=8ks+lc, d=8ks+lc+4)
    // Pre-scaled by 0.125 * log2(e) so scores are in the log2 domain.
    const float QSC = 0.125f * 1.4426950408889634f;
    uint32_t qf[8][4];
    {
        const float* q0 = qb + (size_t)(w * 16 + lr) * ldq;
        const float* q1 = q0 + (size_t)8 * ldq;
        #pragma unroll
        for (int ks = 0; ks < 8; ks++) {
            float2 f0 = *reinterpret_cast<const float2*>(q0 + ks * 8 + 2 * lc);
            float2 f1 = *reinterpret_cast<const float2*>(q1 + ks * 8 + 2 * lc);
            qf[ks][0] = f2tf32(f0.x * QSC);
            qf[ks][1] = f2tf32(f1.x * QSC);
            qf[ks][2] = f2tf32(f0.y * QSC);
            qf[ks][3] = f2tf32(f1.y * QSC);
        }
    }

    load_kv(0, 0);

    float o[8][4] = {};
    float mA = -CUDART_INF_F, mB = -CUDART_INF_F;
    float lA = 0.f, lB = 0.f;          // per-thread partial row sums

    const int lrow = w * 16 + lr;       // local q row (0..127)
    const int nkt  = 2 * qt + 2;        // number of 64-key tiles

    for (int kt = 0; kt < nkt; kt++) {
        const int cur = kt & 1;
        __syncthreads();                  // buf cur^1 readers (kt-1) done
        const int has_next = (kt + 1 < nkt);
        if (has_next) load_kv(cur ^ 1, kt + 1);
        cp_wait(has_next);                // K/V(kt) arrived
        __syncthreads();                  // visible to all warps

        const uint32_t* KPb = dynsmem + cur * KPSZ;
        const uint32_t* Vsb = dynsmem + 2 * KPSZ + cur * VSZ;

        // ---- S = Q @ K^T (K HD-permuted -> LDS.64 b-fragments) ----
        float s[8][4] = {};
        #pragma unroll
        for (int ks = 0; ks < 8; ks++) {
            const int kk = ks * 8;
            #pragma unroll
            for (int ni = 0; ni < 8; ni++) {
                uint2 bb = *reinterpret_cast<const uint2*>(
                    &KPb[(ni * 8 + lr) * KST + kk + 2 * lc]);
                mma_tf32(s[ni], qf[ks][0], qf[ks][1], qf[ks][2], qf[ks][3], bb.x, bb.y);
            }
        }

        // Causal mask: only the last two key tiles can cross the diagonal
        if (kt >= 2 * qt) {
            const int coff = (kt - 2 * qt) << 6;   // 0 or 64
            #pragma unroll
            for (int ni = 0; ni < 8; ni++) {
                int c0 = coff + ni * 8 + 2 * lc;
                int c1 = c0 + 1;
                if (c0 > lrow)     s[ni][0] = -CUDART_INF_F;
                if (c1 > lrow)     s[ni][1] = -CUDART_INF_F;
                if (c0 > lrow + 8) s[ni][2] = -CUDART_INF_F;
                if (c1 > lrow + 8) s[ni][3] = -CUDART_INF_F;
            }
        }

        // ---- online softmax (log2 domain), P stays in registers ----
        float mxA = -CUDART_INF_F, mxB = -CUDART_INF_F;
        #pragma unroll
        for (int ni = 0; ni < 8; ni++) {
            mxA = fmaxf(mxA, fmaxf(s[ni][0], s[ni][1]));
            mxB = fmaxf(mxB, fmaxf(s[ni][2], s[ni][3]));
        }
        #pragma unroll
        for (int off = 1; off <= 2; off <<= 1) {
            mxA = fmaxf(mxA, __shfl_xor_sync(0xffffffffu, mxA, off));
            mxB = fmaxf(mxB, __shfl_xor_sync(0xffffffffu, mxB, off));
        }
        const float mnA = fmaxf(mA, mxA);
        const float mnB = fmaxf(mB, mxB);
        const float cA = ex2(mA - mnA);
        const float cB = ex2(mB - mnB);
        mA = mnA;  mB = mnB;
        #pragma unroll
        for (int ni = 0; ni < 8; ni++) {
            o[ni][0] *= cA;  o[ni][1] *= cA;
            o[ni][2] *= cB;  o[ni][3] *= cB;
        }

        // ---- fused ex2 + PV: for each key group kg, s[kg] IS the A-frag ----
        float rsA = 0.f, rsB = 0.f;
        #pragma unroll
        for (int kg = 0; kg < 8; kg++) {
            const int kk = kg * 8;
            float p0 = ex2(s[kg][0] - mnA);
            float p1 = ex2(s[kg][1] - mnA);
            float p2 = ex2(s[kg][2] - mnB);
            float p3 = ex2(s[kg][3] - mnB);
            rsA += p0 + p1;
            rsB += p2 + p3;
            uint32_t a0 = f2tf32(p0);
            uint32_t a1 = f2tf32(p2);
            uint32_t a2 = f2tf32(p1);
            uint32_t a3 = f2tf32(p3);
            #pragma unroll
            for (int ni = 0; ni < 8; ni++) {
                uint32_t b0 = Vsb[(kk + lc) * VST + ni * 8 + lr];
                uint32_t b1 = Vsb[(kk + lc + 4) * VST + ni * 8 + lr];
                mma_tf32(o[ni], a0, a1, a2, a3, b0, b1);
            }
        }
        lA = lA * cA + rsA;
        lB = lB * cB + rsB;
    }

    // Epilogue: quad-reduce partial sums, normalize, tf32-round, write permuted
    #pragma unroll
    for (int off = 1; off <= 2; off <<= 1) {
        lA += __shfl_xor_sync(0xffffffffu, lA, off);
        lB += __shfl_xor_sync(0xffffffffu, lB, off);
    }
    const float iA = 1.0f / lA;
    const float iB = 1.0f / lB;
    const int p0 = ((2 * lc) & 3) * 2 + ((2 * lc) >> 2);
    const int p1 = ((2 * lc + 1) & 3) * 2 + ((2 * lc + 1) >> 2);
    float* obA = g_attn + ((size_t)b * SS + (size_t)qt * 128 + lrow) * DD + h * HDIM;
    float* obB = obA + (size_t)8 * DD;
    #pragma unroll
    for (int ni = 0; ni < 8; ni++) {
        uint32_t* dA = (uint32_t*)(obA + ni * 8);
        uint32_t* dB = (uint32_t*)(obB + ni * 8);
        dA[p0] = f2tf32(o[ni][0] * iA);
        dA[p1] = f2tf32(o[ni][1] * iA);
        dB[p0] = f2tf32(o[ni][2] * iB);
        dB[p1] = f2tf32(o[ni][3] * iB);
    }
}

// ---------------------------------------------------------------------------
extern "C" void kernel_launch(void* const* d_in, const int* in_sizes, int n_in,
                              void* d_out, int out_size)
{
    const float* x    = (const float*)d_in[0];  // (2,2048,1024)
    const float* wqkv = (const float*)d_in[1];  // (1024,3072)
    const float* wout = (const float*)d_in[2];  // (1024,1024)
    float* out = (float*)d_out;                 // (2,2048,1024)

    const int GEMM_SMEM = (3 * STAGE) * 4;           // 113664
    const int ATTN_SMEM = (2 * KPSZ + 2 * VSZ) * 4;  // 73728
    cudaFuncSetAttribute(mma_gemm<0>, cudaFuncAttributeMaxDynamicSharedMemorySize, GEMM_SMEM);
    cudaFuncSetAttribute(mma_gemm<1>, cudaFuncAttributeMaxDynamicSharedMemorySize, GEMM_SMEM);
    cudaFuncSetAttribute(attn_mma,    cudaFuncAttributeMaxDynamicSharedMemorySize, ATTN_SMEM);

    // 0) Round to tf32 once (x also gets the k-pair permutation)
    pre_round<<<2048, 256>>>((const float4*)x, (const float4*)wqkv, (const float4*)wout);

    // 1) QKV projection -> g_qkv
    mma_gemm<0><<<dim3(NQKV / 128, MROWS / 128), 256, GEMM_SMEM>>>(nullptr);

    // 2) Causal attention -> g_attn  [128-row q-tiles, 8 warps, register-P]
    attn_mma<<<dim3(SS / 128, HH, BB), 256, ATTN_SMEM>>>();

    // 3) Output projection -> d_out (fp32)
    mma_gemm<1><<<dim3(DD / 128, MROWS / 128), 256, GEMM_SMEM>>>(out);
}

// round 17
// speedup vs baseline: 1.0533x; 1.0533x over previous
#include <cuda_runtime.h>
#include <math_constants.h>
#include <stdint.h>

// Problem constants
#define BB 2
#define SS 2048
#define DD 1024
#define HH 16
#define HDIM 64
#define MROWS (BB * SS)      // 4096
#define NQKV (3 * DD)        // 3072

// Scratch (allocation-free rule: __device__ globals)
// k-pair permutation pi(j) = 2*(j&3) + (j>>2) applied within 8-groups of the
// contraction index on A-operand producers:
//   g_xr   : x with D-columns permuted
//   g_qkv  : Q,K thirds have HD-columns permuted; V third plain
//   g_attn : D-columns permuted (feeds outproj A)
__device__ float g_qkv[(size_t)MROWS * NQKV];
__device__ float g_attn[(size_t)MROWS * DD];
__device__ float g_xr[(size_t)MROWS * DD];
__device__ float g_wqkvr[(size_t)DD * NQKV];    // tf32-rounded w_qkv (plain)
__device__ float g_woutr[(size_t)DD * DD];      // tf32-rounded w_out (plain)

__device__ __forceinline__ uint32_t f2tf32(float f) {
    uint32_t u;
    asm("cvt.rna.tf32.f32 %0, %1;" : "=r"(u) : "f"(f));
    return u;
}

__device__ __forceinline__ float ex2(float x) {
    float r;
    asm("ex2.approx.f32 %0, %1;" : "=f"(r) : "f"(x));
    return r;
}

__device__ __forceinline__ void mma_tf32(float d[4],
                                         uint32_t a0, uint32_t a1, uint32_t a2, uint32_t a3,
                                         uint32_t b0, uint32_t b1) {
    asm volatile(
        "mma.sync.aligned.m16n8k8.row.col.f32.tf32.tf32.f32 "
        "{%0,%1,%2,%3}, {%4,%5,%6,%7}, {%8,%9}, {%0,%1,%2,%3};"
        : "+f"(d[0]), "+f"(d[1]), "+f"(d[2]), "+f"(d[3])
        : "r"(a0), "r"(a1), "r"(a2), "r"(a3), "r"(b0), "r"(b1));
}

__device__ __forceinline__ void cp16(uint32_t dst_smem, const void* src) {
    asm volatile("cp.async.cg.shared.global [%0], [%1], 16;"
                 :: "r"(dst_smem), "l"(src));
}
__device__ __forceinline__ void cp_commit() {
    asm volatile("cp.async.commit_group;" ::: "memory");
}
template <int N>
__device__ __forceinline__ void cp_wait_n() {
    asm volatile("cp.async.wait_group %0;" :: "n"(N) : "memory");
}

// ---------------------------------------------------------------------------
// Pre-round inputs to tf32. x additionally gets the k-pair permutation:
// per 8-group [j0..j7] -> [j0,j4,j1,j5,j2,j6,j3,j7].
// ---------------------------------------------------------------------------
__global__ __launch_bounds__(256)
void pre_round(const float4* __restrict__ x,
               const float4* __restrict__ wq,
               const float4* __restrict__ wo)
{
    const int NX8 = (MROWS * DD) / 8;       // 8-float granules of x
    const int NQ  = (DD * NQKV) / 4;
    const int NO  = (DD * DD) / 4;
    for (int i = blockIdx.x * blockDim.x + threadIdx.x;
         i < NX8 + NQ + NO; i += gridDim.x * blockDim.x) {
        if (i < NX8) {
            float4 lo = x[2 * i], hi = x[2 * i + 1];
            uint4 t0 = make_uint4(f2tf32(lo.x), f2tf32(hi.x), f2tf32(lo.y), f2tf32(hi.y));
            uint4 t1 = make_uint4(f2tf32(lo.z), f2tf32(hi.z), f2tf32(lo.w), f2tf32(hi.w));
            ((float4*)g_xr)[2 * i]     = *reinterpret_cast<float4*>(&t0);
            ((float4*)g_xr)[2 * i + 1] = *reinterpret_cast<float4*>(&t1);
        } else if (i < NX8 + NQ) {
            float4 v = wq[i - NX8];
            uint4 t = make_uint4(f2tf32(v.x), f2tf32(v.y), f2tf32(v.z), f2tf32(v.w));
            ((float4*)g_wqkvr)[i - NX8] = *reinterpret_cast<float4*>(&t);
        } else {
            float4 v = wo[i - NX8 - NQ];
            uint4 t = make_uint4(f2tf32(v.x), f2tf32(v.y), f2tf32(v.z), f2tf32(v.w));
            ((float4*)g_woutr)[i - NX8 - NQ] = *reinterpret_cast<float4*>(&t);
        }
    }
}

// ---------------------------------------------------------------------------
// TF32 tensor-core GEMM, 3-stage cp.async pipeline (unchanged champion).
// ---------------------------------------------------------------------------
#define ASTR 40
#define ASZ (128 * ASTR)
#define BSZ (32 * 136)
#define STAGE (ASZ + BSZ)

template <int MODE>
__global__ __launch_bounds__(256, 2)
void mma_gemm(float* __restrict__ Cp)
{
    extern __shared__ uint32_t dynsmem[];
    constexpr int N_ = (MODE == 0) ? NQKV : DD;
    constexpr int K_ = DD;
    constexpr int NK = K_ / 32;            // 32

    const float* A  = (MODE == 0) ? (const float*)g_xr    : (const float*)g_attn;
    const float* Bm = (MODE == 0) ? (const float*)g_wqkvr : (const float*)g_woutr;
    float* C = (MODE == 0) ? (float*)g_qkv : Cp;

    const int tid  = threadIdx.x;
    const int warp = tid >> 5;
    const int lane = tid & 31;
    const int r = lane >> 2;
    const int c = lane & 3;

    const int bm = blockIdx.y * 128;
    const int bn = blockIdx.x * 128;
    const int wm = (warp >> 2) * 64;
    const int wn = (warp & 3) * 32;

    const uint32_t smem_base = (uint32_t)__cvta_generic_to_shared(dynsmem);

    float acc[4][4][4] = {};

    auto load_tiles = [&](int st, int k0) {
        uint32_t abase = smem_base + (uint32_t)(st * STAGE) * 4u;
        uint32_t bbase = abase + (uint32_t)ASZ * 4u;
        #pragma unroll
        for (int p = 0; p < 4; p++) {
            int f4 = tid + p * 256;
            int rr = f4 >> 3;
            int cc = (f4 & 7) << 2;
            cp16(abase + (uint32_t)(rr * ASTR + cc) * 4u,
                 A + (size_t)(bm + rr) * K_ + k0 + cc);
        }
        #pragma unroll
        for (int p = 0; p < 4; p++) {
            int f4 = tid + p * 256;
            int rr = f4 >> 5;
            int cc = (f4 & 31) << 2;
            cp16(bbase + (uint32_t)(rr * 136 + cc) * 4u,
                 Bm + (size_t)(k0 + rr) * N_ + bn + cc);
        }
        cp_commit();
    };

    load_tiles(0, 0);
    load_tiles(1, 32);

    int st = 0;
    for (int i = 0; i < NK; i++) {
        if (i + 1 < NK) cp_wait_n<1>();   // load(i) complete; load(i+1) in flight
        else            cp_wait_n<0>();
        __syncthreads();                  // compute(i-1) readers of buf st2 done
        if (i + 2 < NK) {
            int st2 = st + 2; if (st2 >= 3) st2 -= 3;
            load_tiles(st2, (i + 2) << 5);
        }

        const uint32_t* Asb = dynsmem + st * STAGE;
        const uint32_t* Bsb = Asb + ASZ;

        #pragma unroll
        for (int ks = 0; ks < 4; ks++) {
            const int kk = ks * 8;
            uint32_t af[4][4], bf[4][2];
            #pragma unroll
            for (int mi = 0; mi < 4; mi++) {
                int row = wm + mi * 16 + r;
                uint2 aa0 = *reinterpret_cast<const uint2*>(&Asb[row * ASTR + kk + 2 * c]);
                uint2 aa1 = *reinterpret_cast<const uint2*>(&Asb[(row + 8) * ASTR + kk + 2 * c]);
                af[mi][0] = aa0.x; af[mi][1] = aa1.x;
                af[mi][2] = aa0.y; af[mi][3] = aa1.y;
            }
            #pragma unroll
            for (int ni = 0; ni < 4; ni++) {
                int col = wn + ni * 8 + r;
                bf[ni][0] = Bsb[(kk + c) * 136 + col];
                bf[ni][1] = Bsb[(kk + c + 4) * 136 + col];
            }
            #pragma unroll
            for (int mi = 0; mi < 4; mi++)
                #pragma unroll
                for (int ni = 0; ni < 4; ni++)
                    mma_tf32(acc[mi][ni], af[mi][0], af[mi][1], af[mi][2], af[mi][3],
                             bf[ni][0], bf[ni][1]);
        }
        if (++st == 3) st = 0;
    }

    const int p0 = ((2 * c) & 3) * 2 + ((2 * c) >> 2);
    const int p1 = ((2 * c + 1) & 3) * 2 + ((2 * c + 1) >> 2);
    #pragma unroll
    for (int mi = 0; mi < 4; mi++) {
        int row0 = bm + wm + mi * 16 + r;
        #pragma unroll
        for (int ni = 0; ni < 4; ni++) {
            if (MODE == 0) {
                uint32_t v0 = f2tf32(acc[mi][ni][0]);
                uint32_t v1 = f2tf32(acc[mi][ni][1]);
                uint32_t v2 = f2tf32(acc[mi][ni][2]);
                uint32_t v3 = f2tf32(acc[mi][ni][3]);
                if (bn < 2 * DD) {     // Q or K third: permuted scatter
                    int gb = bn + wn + ni * 8;
                    uint32_t* c0 = (uint32_t*)(C + (size_t)row0 * N_ + gb);
                    uint32_t* c1 = (uint32_t*)(C + (size_t)(row0 + 8) * N_ + gb);
                    c0[p0] = v0;  c0[p1] = v1;
                    c1[p0] = v2;  c1[p1] = v3;
                } else {               // V third: plain
                    int col = bn + wn + ni * 8 + c * 2;
                    *reinterpret_cast<uint2*>(C + (size_t)row0 * N_ + col) = make_uint2(v0, v1);
                    *reinterpret_cast<uint2*>(C + (size_t)(row0 + 8) * N_ + col) = make_uint2(v2, v3);
                }
            } else {
                int col = bn + wn + ni * 8 + c * 2;
                *reinterpret_cast<float2*>(Cp + (size_t)row0 * N_ + col) =
                    make_float2(acc[mi][ni][0], acc[mi][ni][1]);
                *reinterpret_cast<float2*>(Cp + (size_t)(row0 + 8) * N_ + col) =
                    make_float2(acc[mi][ni][2], acc[mi][ni][3]);
            }
        }
    }
}

// ---------------------------------------------------------------------------
// TF32 causal flash attention — register-P, log2 softmax (R14 champion math),
// SINGLE barrier per key tile (clean re-measure of the R11 structure whose
// only prior datapoint was clock-contaminated):
//   per kt: wait_group(0)  [load(kt) complete — it was issued last iteration
//                           and overlapped compute(kt-1), so this is ~free]
//           __syncthreads  [K/V(kt) visible AND iter kt-1's readers of buf
//                           cur^1 proven done -> WAR-safe]
//           issue load(kt+1) -> buf cur^1   [overlaps compute(kt)]
//           S(kt) -> softmax(kt) -> PV(kt)
// 64-row q-tiles, 128 threads, 3 CTAs/SM (the proven-optimal geometry).
// ---------------------------------------------------------------------------
#define KST 72
#define VST 72
#define KPSZ (64 * KST)
#define VSZ  (64 * VST)

__global__ __launch_bounds__(128, 3)
void attn_mma(void)
{
    extern __shared__ uint32_t dynsmem[];

    const int tid = threadIdx.x;
    const int w  = tid >> 5;
    const int l  = tid & 31;
    const int lr = l >> 2;
    const int lc = l & 3;
    const int qt = gridDim.x - 1 - blockIdx.x;   // long blocks first
    const int h  = blockIdx.y;
    const int b  = blockIdx.z;
    const int ldq = NQKV;

    const float* qb  = g_qkv + ((size_t)b * SS + (size_t)qt * 64) * ldq + h * HDIM;
    const float* kb0 = g_qkv + (size_t)b * SS * ldq + DD + h * HDIM;
    const float* vb0 = g_qkv + (size_t)b * SS * ldq + 2 * DD + h * HDIM;

    const uint32_t smem_base = (uint32_t)__cvta_generic_to_shared(dynsmem);

    auto load_kv = [&](int st, int kt) {
        const float* kb = kb0 + (size_t)kt * 64 * ldq;
        const float* vb = vb0 + (size_t)kt * 64 * ldq;
        uint32_t kbase = smem_base + (uint32_t)(st * KPSZ) * 4u;
        uint32_t vbase = smem_base + (uint32_t)(2 * KPSZ + st * VSZ) * 4u;
        #pragma unroll
        for (int p = 0; p < 8; p++) {
            int f4 = tid + p * 128;
            int r  = f4 >> 4;
            int c4 = (f4 & 15) << 2;
            cp16(kbase + (uint32_t)(r * KST + c4) * 4u, kb + (size_t)r * ldq + c4);
            // V: permuted key-row slot  sigma(r&7) = 4*(r&1) + ((r&7)>>1)
            int vr = (r & 56) | (((r & 1) << 2) | ((r & 7) >> 1));
            cp16(vbase + (uint32_t)(vr * VST + c4) * 4u, vb + (size_t)r * ldq + c4);
        }
        cp_commit();
    };

    // Q fragments: permuted pair (2lc,2lc+1) == original (d=8ks+lc, d=8ks+lc+4)
    // Pre-scaled by 0.125 * log2(e) so scores are in the log2 domain.
    const float QSC = 0.125f * 1.4426950408889634f;
    uint32_t qf[8][4];
    {
        const float* q0 = qb + (size_t)(w * 16 + lr) * ldq;
        const float* q1 = q0 + (size_t)8 * ldq;
        #pragma unroll
        for (int ks = 0; ks < 8; ks++) {
            float2 f0 = *reinterpret_cast<const float2*>(q0 + ks * 8 + 2 * lc);
            float2 f1 = *reinterpret_cast<const float2*>(q1 + ks * 8 + 2 * lc);
            qf[ks][0] = f2tf32(f0.x * QSC);
            qf[ks][1] = f2tf32(f1.x * QSC);
            qf[ks][2] = f2tf32(f0.y * QSC);
            qf[ks][3] = f2tf32(f1.y * QSC);
        }
    }

    load_kv(0, 0);

    float o[8][4] = {};
    float mA = -CUDART_INF_F, mB = -CUDART_INF_F;
    float lA = 0.f, lB = 0.f;          // per-thread partial row sums

    const int rowA = w * 16 + lr;
    const int rowB = rowA + 8;

    for (int kt = 0; kt <= qt; kt++) {
        const int cur = kt & 1;
        cp_wait_n<0>();                   // load(kt) done (issued last iteration)
        __syncthreads();                  // visible; kt-1 readers of buf cur^1 done
        if (kt < qt) load_kv(cur ^ 1, kt + 1);   // overlaps compute(kt)

        const uint32_t* KPb = dynsmem + cur * KPSZ;
        const uint32_t* Vsb = dynsmem + 2 * KPSZ + cur * VSZ;

        // ---- S = Q @ K^T (K HD-permuted -> LDS.64 b-fragments) ----
        float s[8][4] = {};
        #pragma unroll
        for (int ks = 0; ks < 8; ks++) {
            const int kk = ks * 8;
            #pragma unroll
            for (int ni = 0; ni < 8; ni++) {
                uint2 bb = *reinterpret_cast<const uint2*>(
                    &KPb[(ni * 8 + lr) * KST + kk + 2 * lc]);
                mma_tf32(s[ni], qf[ks][0], qf[ks][1], qf[ks][2], qf[ks][3], bb.x, bb.y);
            }
        }

        if (kt == qt) {
            #pragma unroll
            for (int ni = 0; ni < 8; ni++) {
                int c0 = ni * 8 + 2 * lc;
                int c1 = c0 + 1;
                if (c0 > rowA) s[ni][0] = -CUDART_INF_F;
                if (c1 > rowA) s[ni][1] = -CUDART_INF_F;
                if (c0 > rowB) s[ni][2] = -CUDART_INF_F;
                if (c1 > rowB) s[ni][3] = -CUDART_INF_F;
            }
        }

        // ---- online softmax (log2 domain), P stays in registers ----
        float mxA = -CUDART_INF_F, mxB = -CUDART_INF_F;
        #pragma unroll
        for (int ni = 0; ni < 8; ni++) {
            mxA = fmaxf(mxA, fmaxf(s[ni][0], s[ni][1]));
            mxB = fmaxf(mxB, fmaxf(s[ni][2], s[ni][3]));
        }
        #pragma unroll
        for (int off = 1; off <= 2; off <<= 1) {
            mxA = fmaxf(mxA, __shfl_xor_sync(0xffffffffu, mxA, off));
            mxB = fmaxf(mxB, __shfl_xor_sync(0xffffffffu, mxB, off));
        }
        const float mnA = fmaxf(mA, mxA);
        const float mnB = fmaxf(mB, mxB);
        const float cA = ex2(mA - mnA);
        const float cB = ex2(mB - mnB);
        mA = mnA;  mB = mnB;
        #pragma unroll
        for (int ni = 0; ni < 8; ni++) {
            o[ni][0] *= cA;  o[ni][1] *= cA;
            o[ni][2] *= cB;  o[ni][3] *= cB;
        }

        // ---- fused ex2 + PV: for each key group kg, s[kg] IS the A-frag ----
        float rsA = 0.f, rsB = 0.f;
        #pragma unroll
        for (int kg = 0; kg < 8; kg++) {
            const int kk = kg * 8;
            float p0 = ex2(s[kg][0] - mnA);
            float p1 = ex2(s[kg][1] - mnA);
            float p2 = ex2(s[kg][2] - mnB);
            float p3 = ex2(s[kg][3] - mnB);
            rsA += p0 + p1;
            rsB += p2 + p3;
            uint32_t a0 = f2tf32(p0);
            uint32_t a1 = f2tf32(p2);
            uint32_t a2 = f2tf32(p1);
            uint32_t a3 = f2tf32(p3);
            #pragma unroll
            for (int ni = 0; ni < 8; ni++) {
                uint32_t b0 = Vsb[(kk + lc) * VST + ni * 8 + lr];
                uint32_t b1 = Vsb[(kk + lc + 4) * VST + ni * 8 + lr];
                mma_tf32(o[ni], a0, a1, a2, a3, b0, b1);
            }
        }
        lA = lA * cA + rsA;
        lB = lB * cB + rsB;
    }

    // Epilogue: quad-reduce partial sums, normalize, tf32-round, write permuted
    #pragma unroll
    for (int off = 1; off <= 2; off <<= 1) {
        lA += __shfl_xor_sync(0xffffffffu, lA, off);
        lB += __shfl_xor_sync(0xffffffffu, lB, off);
    }
    const float iA = 1.0f / lA;
    const float iB = 1.0f / lB;
    const int p0 = ((2 * lc) & 3) * 2 + ((2 * lc) >> 2);
    const int p1 = ((2 * lc + 1) & 3) * 2 + ((2 * lc + 1) >> 2);
    float* obA = g_attn + ((size_t)b * SS + (size_t)qt * 64 + rowA) * DD + h * HDIM;
    float* obB = obA + (size_t)8 * DD;
    #pragma unroll
    for (int ni = 0; ni < 8; ni++) {
        uint32_t* dA = (uint32_t*)(obA + ni * 8);
        uint32_t* dB = (uint32_t*)(obB + ni * 8);
        dA[p0] = f2tf32(o[ni][0] * iA);
        dA[p1] = f2tf32(o[ni][1] * iA);
        dB[p0] = f2tf32(o[ni][2] * iB);
        dB[p1] = f2tf32(o[ni][3] * iB);
    }
}

// ---------------------------------------------------------------------------
extern "C" void kernel_launch(void* const* d_in, const int* in_sizes, int n_in,
                              void* d_out, int out_size)
{
    const float* x    = (const float*)d_in[0];  // (2,2048,1024)
    const float* wqkv = (const float*)d_in[1];  // (1024,3072)
    const float* wout = (const float*)d_in[2];  // (1024,1024)
    float* out = (float*)d_out;                 // (2,2048,1024)

    const int GEMM_SMEM = (3 * STAGE) * 4;           // 113664
    const int ATTN_SMEM = (2 * KPSZ + 2 * VSZ) * 4;  // 73728
    cudaFuncSetAttribute(mma_gemm<0>, cudaFuncAttributeMaxDynamicSharedMemorySize, GEMM_SMEM);
    cudaFuncSetAttribute(mma_gemm<1>, cudaFuncAttributeMaxDynamicSharedMemorySize, GEMM_SMEM);
    cudaFuncSetAttribute(attn_mma,    cudaFuncAttributeMaxDynamicSharedMemorySize, ATTN_SMEM);

    // 0) Round to tf32 once (x also gets the k-pair permutation)
    pre_round<<<2048, 256>>>((const float4*)x, (const float4*)wqkv, (const float4*)wout);

    // 1) QKV projection -> g_qkv
    mma_gemm<0><<<dim3(NQKV / 128, MROWS / 128), 256, GEMM_SMEM>>>(nullptr);

    // 2) Causal attention -> g_attn  [register-P, log2 softmax, 1 barrier/tile]
    attn_mma<<<dim3(SS / 64, HH, BB), 128, ATTN_SMEM>>>();

    // 3) Output projection -> d_out (fp32)
    mma_gemm<1><<<dim3(DD / 128, MROWS / 128), 256, GEMM_SMEM>>>(out);
}